// round 3
// baseline (speedup 1.0000x reference)
#include <cuda_runtime.h>
#include <cstdint>

// Problem constants
#define Bb   8
#define Np   8192
#define Sp   2048
#define Kp   32
#define Dp   128
#define C0   131          // D + 3
#define C0P  132          // padded
#define M0   128
#define M1   128
#define M2   256
#define HIDp 8
#define LEAKYF 0.1f
#define FLATN (M2*HIDp)   // 2048

// Scratch (device globals: allocation-free rule)
__device__ float g_flat[(size_t)Bb * Sp * FLATN];   // 134 MB
__device__ float g_ptsT[(size_t)Bb * Np * Dp];      // 32 MB  [b][n][c]
__device__ int   g_knn[Bb * Sp * Kp];               // 2 MB
__device__ float g_w1p[M0 * C0P];                   // padded w1 (stride 132)

__device__ __forceinline__ float lrelu(float x) { return x > 0.0f ? x : LEAKYF * x; }

// ---------------------------------------------------------------------------
// Kernel P: pad w1 [128][131] -> g_w1p [128][132] (col 131 = 0)
// ---------------------------------------------------------------------------
__global__ void prep_w1_kernel(const float* __restrict__ w1)
{
    int idx = blockIdx.x * blockDim.x + threadIdx.x;
    if (idx >= M0 * C0P) return;
    int o = idx / C0P, c = idx - o * C0P;
    g_w1p[idx] = (c < C0) ? w1[o * C0 + c] : 0.0f;
}

// ---------------------------------------------------------------------------
// Kernel 0: copy new_xyz = xyz[:, :, :S] to output head
// ---------------------------------------------------------------------------
__global__ void copy_newxyz_kernel(const float* __restrict__ xyz, float* __restrict__ out)
{
    int idx = blockIdx.x * blockDim.x + threadIdx.x;
    if (idx >= Bb * 3 * Sp) return;
    int b = idx / (3 * Sp);
    int r = idx - b * 3 * Sp;
    int c = r / Sp;
    int s = r - c * Sp;
    out[idx] = xyz[(b * 3 + c) * Np + s];
}

// ---------------------------------------------------------------------------
// Kernel 1: transpose points [B][D][N] -> ptsT [B][N][D]
// ---------------------------------------------------------------------------
__global__ void transpose_kernel(const float* __restrict__ p)
{
    __shared__ float tile[32][33];
    int b  = blockIdx.z;
    int nb = blockIdx.x * 32;
    int cb = blockIdx.y * 32;
    int tx = threadIdx.x;
    int ty = threadIdx.y;
    const float* src = p + (size_t)b * Dp * Np;
    float* dst = g_ptsT + (size_t)b * Np * Dp;
    #pragma unroll
    for (int j = ty; j < 32; j += 8)
        tile[j][tx] = src[(size_t)(cb + j) * Np + nb + tx];
    __syncthreads();
    #pragma unroll
    for (int j = ty; j < 32; j += 8)
        dst[(size_t)(nb + j) * Dp + cb + tx] = tile[tx][j];
}

// ---------------------------------------------------------------------------
// Kernel 2: KNN (matches jax top_k(-sqr) with index tie-break)
// ---------------------------------------------------------------------------
__global__ void __launch_bounds__(256) knn_kernel(const float* __restrict__ xyz)
{
    const int bs = blockIdx.x;
    const int b  = bs >> 11;
    const int s  = bs & (Sp - 1);
    const float* X = xyz + (size_t)b * 3 * Np;
    const int t = threadIdx.x;

    const float qx = X[s], qy = X[Np + s], qz = X[2 * Np + s];
    const float qq = qx * qx + qy * qy + qz * qz;

    float d[32];
    #pragma unroll
    for (int i = 0; i < 32; i++) {
        int n = t + (i << 8);
        float px = X[n], py = X[Np + n], pz = X[2 * Np + n];
        float pp  = px * px + py * py + pz * pz;
        float dot = qx * px + qy * py + qz * pz;
        d[i] = (qq + pp) - 2.0f * dot;
    }

    float lbv = d[0]; int lbs = 0;
    #pragma unroll
    for (int i = 1; i < 32; i++) if (d[i] < lbv) { lbv = d[i]; lbs = i; }

    __shared__ float bv[256];
    __shared__ int   bi[256];
    __shared__ int   s_sel[Kp];
    __shared__ int   s_cur;

    for (int r = 0; r < Kp; r++) {
        bv[t] = lbv;
        bi[t] = t + (lbs << 8);
        __syncthreads();
        if (t < 32) {
            float v = bv[t]; int id = bi[t];
            #pragma unroll
            for (int j = 1; j < 8; j++) {
                float v2 = bv[t + 32 * j]; int i2 = bi[t + 32 * j];
                if (v2 < v || (v2 == v && i2 < id)) { v = v2; id = i2; }
            }
            #pragma unroll
            for (int off = 16; off > 0; off >>= 1) {
                float v2 = __shfl_down_sync(0xffffffffu, v, off);
                int   i2 = __shfl_down_sync(0xffffffffu, id, off);
                if (v2 < v || (v2 == v && i2 < id)) { v = v2; id = i2; }
            }
            if (t == 0) { s_sel[r] = id; s_cur = id; }
        }
        __syncthreads();
        int cid = s_cur;
        if ((cid & 255) == t) {
            int slot = cid >> 8;
            #pragma unroll
            for (int i = 0; i < 32; i++) if (i == slot) d[i] = 3.0e38f;
            lbv = d[0]; lbs = 0;
            #pragma unroll
            for (int i = 1; i < 32; i++) if (d[i] < lbv) { lbv = d[i]; lbs = i; }
        }
    }
    if (t < Kp) g_knn[bs * Kp + t] = s_sel[t];
}

// ---------------------------------------------------------------------------
// Kernel 3: per-(b,s) MLP stack, register-tiled 16(o) x 8(k), tile 4k x 8o.
// __launch_bounds__(128, 4): cap regs at 128 -> guaranteed 4 CTAs/SM.
// ---------------------------------------------------------------------------
#define SA  (32*132)
#define SB  (32*260)
#define SMEM_FLOATS (SA + SB + 32*8)
#define SMEM_BYTES  (SMEM_FLOATS*4 + 32*4)

__global__ void __launch_bounds__(128, 4) mlp_kernel(
    const float* __restrict__ xyz,
    const float* __restrict__ w2, const float* __restrict__ w3,
    const float* __restrict__ wn1, const float* __restrict__ wb1,
    const float* __restrict__ wn2, const float* __restrict__ wb2,
    const float* __restrict__ wn3, const float* __restrict__ wb3)
{
    extern __shared__ float sm[];
    float* bufA = sm;               // sfeat / h2  (stride 132)
    float* bufB = sm + SA;          // h1 (stride 132) / h3 (stride 260)
    float* swm  = sm + SA + SB;     // [32][8]
    int*   sidx = (int*)(swm + 32 * 8);

    const int bs = blockIdx.x;
    const int b  = bs >> 11;
    const int s  = bs & (Sp - 1);
    const int t  = threadIdx.x;
    const int ot = t & 15;          // 0..15
    const int kt = t >> 4;          // 0..7
    const int kb = kt * 4;
    const float* X  = xyz + (size_t)b * 3 * Np;
    const float* PT = g_ptsT + (size_t)b * Np * Dp;

    if (t < 32) sidx[t] = g_knn[bs * Kp + t];
    __syncthreads();

    const float qx = X[s], qy = X[Np + s], qz = X[2 * Np + s];

    // gather point features: per k, 128 contiguous floats into cols 3..130
    #pragma unroll 4
    for (int k = 0; k < 32; k++) {
        int n = sidx[k];
        bufA[k * 132 + 3 + t] = PT[(size_t)n * Dp + t];
    }
    // direction (cols 0..2) + zero pad col 131
    if (t < 96) {
        int k = t / 3, c = t - k * 3;
        int n = sidx[k];
        float v;
        if (c == 0)      v = X[n]          - qx;
        else if (c == 1) v = X[Np + n]     - qy;
        else             v = X[2 * Np + n] - qz;
        bufA[k * 132 + c] = v;
    }
    if (t < 32) bufA[t * 132 + 131] = 0.0f;
    __syncthreads();

    // weightnet (warp 0, one thread per k) -> swm[32][8]
    if (t < 32) {
        float dx = bufA[t * 132 + 0], dy = bufA[t * 132 + 1], dz = bufA[t * 132 + 2];
        float h[8], g[8];
        #pragma unroll
        for (int o = 0; o < 8; o++) {
            float a = wn1[o * 3 + 0] * dx + wn1[o * 3 + 1] * dy + wn1[o * 3 + 2] * dz + wb1[o];
            h[o] = a > 0.0f ? a : 0.0f;
        }
        #pragma unroll
        for (int o = 0; o < 8; o++) {
            float a = wb2[o];
            #pragma unroll
            for (int c = 0; c < 8; c++) a += wn2[o * 8 + c] * h[c];
            g[o] = a > 0.0f ? a : 0.0f;
        }
        #pragma unroll
        for (int o = 0; o < 8; o++) {
            float a = wb3[o];
            #pragma unroll
            for (int c = 0; c < 8; c++) a += wn3[o * 8 + c] * g[c];
            swm[t * 8 + o] = a > 0.0f ? a : 0.0f;
        }
    }

    // ---- layer 1: feats[32][132] @ w1p[128][132]^T -> h1 (bufB, stride 132)
    {
        float acc[4][8];
        #pragma unroll
        for (int i = 0; i < 4; i++)
            #pragma unroll
            for (int j = 0; j < 8; j++) acc[i][j] = 0.0f;
        #pragma unroll 2
        for (int c0 = 0; c0 < C0P; c0 += 4) {
            float4 f[4];
            #pragma unroll
            for (int i = 0; i < 4; i++)
                f[i] = *(const float4*)&bufA[(kb + i) * 132 + c0];
            #pragma unroll
            for (int j = 0; j < 8; j++) {
                float4 w = __ldg((const float4*)(g_w1p + (ot + 16 * j) * C0P + c0));
                #pragma unroll
                for (int i = 0; i < 4; i++) {
                    acc[i][j] = fmaf(f[i].x, w.x, acc[i][j]);
                    acc[i][j] = fmaf(f[i].y, w.y, acc[i][j]);
                    acc[i][j] = fmaf(f[i].z, w.z, acc[i][j]);
                    acc[i][j] = fmaf(f[i].w, w.w, acc[i][j]);
                }
            }
        }
        __syncthreads();
        #pragma unroll
        for (int i = 0; i < 4; i++)
            #pragma unroll
            for (int j = 0; j < 8; j++)
                bufB[(kb + i) * 132 + ot + 16 * j] = lrelu(acc[i][j]);
    }
    __syncthreads();

    // ---- layer 2: h1 (bufB) @ w2[128][128]^T -> h2 (bufA, stride 132)
    {
        float acc[4][8];
        #pragma unroll
        for (int i = 0; i < 4; i++)
            #pragma unroll
            for (int j = 0; j < 8; j++) acc[i][j] = 0.0f;
        #pragma unroll 2
        for (int c0 = 0; c0 < M0; c0 += 4) {
            float4 f[4];
            #pragma unroll
            for (int i = 0; i < 4; i++)
                f[i] = *(const float4*)&bufB[(kb + i) * 132 + c0];
            #pragma unroll
            for (int j = 0; j < 8; j++) {
                float4 w = __ldg((const float4*)(w2 + (ot + 16 * j) * M0 + c0));
                #pragma unroll
                for (int i = 0; i < 4; i++) {
                    acc[i][j] = fmaf(f[i].x, w.x, acc[i][j]);
                    acc[i][j] = fmaf(f[i].y, w.y, acc[i][j]);
                    acc[i][j] = fmaf(f[i].z, w.z, acc[i][j]);
                    acc[i][j] = fmaf(f[i].w, w.w, acc[i][j]);
                }
            }
        }
        __syncthreads();
        #pragma unroll
        for (int i = 0; i < 4; i++)
            #pragma unroll
            for (int j = 0; j < 8; j++)
                bufA[(kb + i) * 132 + ot + 16 * j] = lrelu(acc[i][j]);
    }
    __syncthreads();

    // ---- layer 3: h2 (bufA) @ w3[256][128]^T -> h3 (bufB, stride 260)
    #pragma unroll 1
    for (int p = 0; p < 2; p++) {
        float acc[4][8];
        #pragma unroll
        for (int i = 0; i < 4; i++)
            #pragma unroll
            for (int j = 0; j < 8; j++) acc[i][j] = 0.0f;
        #pragma unroll 2
        for (int c0 = 0; c0 < M1; c0 += 4) {
            float4 f[4];
            #pragma unroll
            for (int i = 0; i < 4; i++)
                f[i] = *(const float4*)&bufA[(kb + i) * 132 + c0];
            #pragma unroll
            for (int j = 0; j < 8; j++) {
                float4 w = __ldg((const float4*)(w3 + (size_t)(128 * p + ot + 16 * j) * M1 + c0));
                #pragma unroll
                for (int i = 0; i < 4; i++) {
                    acc[i][j] = fmaf(f[i].x, w.x, acc[i][j]);
                    acc[i][j] = fmaf(f[i].y, w.y, acc[i][j]);
                    acc[i][j] = fmaf(f[i].z, w.z, acc[i][j]);
                    acc[i][j] = fmaf(f[i].w, w.w, acc[i][j]);
                }
            }
        }
        if (p == 0) __syncthreads();
        #pragma unroll
        for (int i = 0; i < 4; i++)
            #pragma unroll
            for (int j = 0; j < 8; j++)
                bufB[(kb + i) * 260 + 128 * p + ot + 16 * j] = lrelu(acc[i][j]);
    }
    __syncthreads();

    // ---- agg: agg[o][j] = sum_k h3[k][o]*swm[k][j]; o = t and t+128
    {
        float ag0[8], ag1[8];
        #pragma unroll
        for (int j = 0; j < 8; j++) { ag0[j] = 0.0f; ag1[j] = 0.0f; }
        #pragma unroll 4
        for (int k = 0; k < 32; k++) {
            float h0 = bufB[k * 260 + t];
            float h1 = bufB[k * 260 + t + 128];
            float4 wa = *(const float4*)&swm[k * 8];
            float4 wb = *(const float4*)&swm[k * 8 + 4];
            ag0[0] = fmaf(h0, wa.x, ag0[0]); ag0[1] = fmaf(h0, wa.y, ag0[1]);
            ag0[2] = fmaf(h0, wa.z, ag0[2]); ag0[3] = fmaf(h0, wa.w, ag0[3]);
            ag0[4] = fmaf(h0, wb.x, ag0[4]); ag0[5] = fmaf(h0, wb.y, ag0[5]);
            ag0[6] = fmaf(h0, wb.z, ag0[6]); ag0[7] = fmaf(h0, wb.w, ag0[7]);
            ag1[0] = fmaf(h1, wa.x, ag1[0]); ag1[1] = fmaf(h1, wa.y, ag1[1]);
            ag1[2] = fmaf(h1, wa.z, ag1[2]); ag1[3] = fmaf(h1, wa.w, ag1[3]);
            ag1[4] = fmaf(h1, wb.x, ag1[4]); ag1[5] = fmaf(h1, wb.y, ag1[5]);
            ag1[6] = fmaf(h1, wb.z, ag1[6]); ag1[7] = fmaf(h1, wb.w, ag1[7]);
        }
        float* fo = g_flat + (size_t)bs * FLATN;
        float4* f4 = (float4*)(fo + t * 8);
        f4[0] = make_float4(ag0[0], ag0[1], ag0[2], ag0[3]);
        f4[1] = make_float4(ag0[4], ag0[5], ag0[6], ag0[7]);
        float4* g4 = (float4*)(fo + (t + 128) * 8);
        g4[0] = make_float4(ag1[0], ag1[1], ag1[2], ag1[3]);
        g4[1] = make_float4(ag1[4], ag1[5], ag1[6], ag1[7]);
    }
}

// ---------------------------------------------------------------------------
// Kernel 4: out = lrelu(flat[16384,2048] @ wlin[256,2048]^T) -> out[b][o][s]
// ---------------------------------------------------------------------------
#define BM 64
#define BN 64
#define BKk 16

__global__ void __launch_bounds__(256) out_gemm_kernel(
    const float* __restrict__ Wl, float* __restrict__ outp)
{
    __shared__ float As[BKk][BM];
    __shared__ float Bs[BKk][BN];

    const int bm = blockIdx.x;
    const int bn = blockIdx.y;
    const int t  = threadIdx.x;
    const int m0 = bm * BM, n0 = bn * BN;
    const int tx = t & 15, ty = t >> 4;
    const int lr = t >> 2;
    const int lc = (t & 3) * 4;

    const float* A = g_flat;

    float acc[4][4];
    #pragma unroll
    for (int i = 0; i < 4; i++)
        #pragma unroll
        for (int j = 0; j < 4; j++) acc[i][j] = 0.0f;

    for (int k0 = 0; k0 < FLATN; k0 += BKk) {
        float4 a = *(const float4*)(A + (size_t)(m0 + lr) * FLATN + k0 + lc);
        As[lc + 0][lr] = a.x; As[lc + 1][lr] = a.y; As[lc + 2][lr] = a.z; As[lc + 3][lr] = a.w;
        float4 bq = *(const float4*)(Wl + (size_t)(n0 + lr) * FLATN + k0 + lc);
        Bs[lc + 0][lr] = bq.x; Bs[lc + 1][lr] = bq.y; Bs[lc + 2][lr] = bq.z; Bs[lc + 3][lr] = bq.w;
        __syncthreads();
        #pragma unroll
        for (int k = 0; k < BKk; k++) {
            float4 av = *(const float4*)&As[k][ty * 4];
            float4 bv = *(const float4*)&Bs[k][tx * 4];
            float aa[4] = {av.x, av.y, av.z, av.w};
            float bb[4] = {bv.x, bv.y, bv.z, bv.w};
            #pragma unroll
            for (int i = 0; i < 4; i++)
                #pragma unroll
                for (int j = 0; j < 4; j++)
                    acc[i][j] += aa[i] * bb[j];
        }
        __syncthreads();
    }

    #pragma unroll
    for (int i = 0; i < 4; i++) {
        int mm = m0 + ty * 4 + i;
        int bb = mm >> 11, ss = mm & (Sp - 1);
        float* ob = outp + (size_t)bb * M2 * Sp + ss;
        #pragma unroll
        for (int j = 0; j < 4; j++) {
            ob[(size_t)(n0 + tx * 4 + j) * Sp] = lrelu(acc[i][j]);
        }
    }
}

// ---------------------------------------------------------------------------
// Launcher
// ---------------------------------------------------------------------------
extern "C" void kernel_launch(void* const* d_in, const int* in_sizes, int n_in,
                              void* d_out, int out_size)
{
    const float* xyz  = (const float*)d_in[0];
    const float* pts  = (const float*)d_in[1];
    const float* w1   = (const float*)d_in[2];
    const float* w2   = (const float*)d_in[3];
    const float* w3   = (const float*)d_in[4];
    const float* wn1  = (const float*)d_in[5];
    const float* wb1  = (const float*)d_in[6];
    const float* wn2  = (const float*)d_in[7];
    const float* wb2  = (const float*)d_in[8];
    const float* wn3  = (const float*)d_in[9];
    const float* wb3  = (const float*)d_in[10];
    const float* wlin = (const float*)d_in[11];
    float* out = (float*)d_out;

    prep_w1_kernel<<<(M0 * C0P + 255) / 256, 256>>>(w1);

    copy_newxyz_kernel<<<(Bb * 3 * Sp + 255) / 256, 256>>>(xyz, out);

    {
        dim3 g(Np / 32, Dp / 32, Bb);
        dim3 blk(32, 8);
        transpose_kernel<<<g, blk>>>(pts);
    }

    knn_kernel<<<Bb * Sp, 256>>>(xyz);

    cudaFuncSetAttribute(mlp_kernel, cudaFuncAttributeMaxDynamicSharedMemorySize, SMEM_BYTES);
    mlp_kernel<<<Bb * Sp, 128, SMEM_BYTES>>>(xyz, w2, w3,
                                             wn1, wb1, wn2, wb2, wn3, wb3);

    {
        dim3 g((Bb * Sp) / BM, M2 / BN);
        out_gemm_kernel<<<g, 256>>>(wlin, out + Bb * 3 * Sp);
    }
}

// round 4
// speedup vs baseline: 2.6019x; 2.6019x over previous
#include <cuda_runtime.h>
#include <cstdint>

// Problem constants
#define Bb   8
#define Np   8192
#define Sp   2048
#define Kp   32
#define Dp   128
#define C0   131          // D + 3
#define C1P  132          // padded layer-1 input channels
#define M0   128
#define M1   128
#define M2   256
#define HIDp 8
#define LEAKYF 0.1f
#define FLATN (M2*HIDp)   // 2048

// MLP tiling
#define QB   2            // queries per CTA
#define RR   (QB*Kp)      // 64 rows (m)
#define RP   68           // padded m-stride (floats)

// Scratch (device globals: allocation-free rule)
__device__ float g_flat[(size_t)Bb * Sp * FLATN];   // 134 MB
__device__ float g_ptsT[(size_t)Bb * Np * Dp];      // 32 MB  [b][n][c]
__device__ int   g_knn[Bb * Sp * Kp];               // 2 MB
__device__ float g_w1T[C1P * M0];                   // c-major w1 [132][128]
__device__ float g_w2T[M0 * M1];                    // c-major w2 [128][128]
__device__ float g_w3T[M1 * M2];                    // c-major w3 [128][256]

__device__ __forceinline__ float lrelu(float x) { return x > 0.0f ? x : LEAKYF * x; }

// ---------------------------------------------------------------------------
// Prep kernels: transpose weights to c-major
// ---------------------------------------------------------------------------
__global__ void prep_w1T_kernel(const float* __restrict__ w1)
{
    int idx = blockIdx.x * blockDim.x + threadIdx.x;   // c*128 + o
    if (idx >= C1P * M0) return;
    int c = idx >> 7, o = idx & 127;
    g_w1T[idx] = (c < C0) ? w1[o * C0 + c] : 0.0f;
}
__global__ void prep_w2T_kernel(const float* __restrict__ w2)
{
    int idx = blockIdx.x * blockDim.x + threadIdx.x;
    if (idx >= M0 * M1) return;
    int c = idx >> 7, o = idx & 127;
    g_w2T[idx] = w2[o * M0 + c];
}
__global__ void prep_w3T_kernel(const float* __restrict__ w3)
{
    int idx = blockIdx.x * blockDim.x + threadIdx.x;   // c*256 + o
    if (idx >= M1 * M2) return;
    int c = idx >> 8, o = idx & 255;
    g_w3T[idx] = w3[o * M1 + c];
}

// ---------------------------------------------------------------------------
// Kernel 0: copy new_xyz = xyz[:, :, :S] to output head
// ---------------------------------------------------------------------------
__global__ void copy_newxyz_kernel(const float* __restrict__ xyz, float* __restrict__ out)
{
    int idx = blockIdx.x * blockDim.x + threadIdx.x;
    if (idx >= Bb * 3 * Sp) return;
    int b = idx / (3 * Sp);
    int r = idx - b * 3 * Sp;
    int c = r / Sp;
    int s = r - c * Sp;
    out[idx] = xyz[(b * 3 + c) * Np + s];
}

// ---------------------------------------------------------------------------
// Kernel 1: transpose points [B][D][N] -> ptsT [B][N][D]
// ---------------------------------------------------------------------------
__global__ void transpose_kernel(const float* __restrict__ p)
{
    __shared__ float tile[32][33];
    int b  = blockIdx.z;
    int nb = blockIdx.x * 32;
    int cb = blockIdx.y * 32;
    int tx = threadIdx.x;
    int ty = threadIdx.y;
    const float* src = p + (size_t)b * Dp * Np;
    float* dst = g_ptsT + (size_t)b * Np * Dp;
    #pragma unroll
    for (int j = ty; j < 32; j += 8)
        tile[j][tx] = src[(size_t)(cb + j) * Np + nb + tx];
    __syncthreads();
    #pragma unroll
    for (int j = ty; j < 32; j += 8)
        dst[(size_t)(nb + j) * Dp + cb + tx] = tile[tx][j];
}

// ---------------------------------------------------------------------------
// Kernel 2: KNN (matches jax top_k(-sqr) set semantics; output order = (d, idx))
// ---------------------------------------------------------------------------
__global__ void __launch_bounds__(256) knn_kernel(const float* __restrict__ xyz)
{
    const int bs = blockIdx.x;
    const int b  = bs >> 11;
    const int s  = bs & (Sp - 1);
    const float* X = xyz + (size_t)b * 3 * Np;
    const int t = threadIdx.x;

    const float qx = X[s], qy = X[Np + s], qz = X[2 * Np + s];
    const float qq = qx * qx + qy * qy + qz * qz;

    float d[32];
    #pragma unroll
    for (int i = 0; i < 32; i++) {
        int n = t + (i << 8);
        float px = X[n], py = X[Np + n], pz = X[2 * Np + n];
        float pp  = px * px + py * py + pz * pz;
        float dot = qx * px + qy * py + qz * pz;
        d[i] = (qq + pp) - 2.0f * dot;
    }

    float lbv = d[0]; int lbs = 0;
    #pragma unroll
    for (int i = 1; i < 32; i++) if (d[i] < lbv) { lbv = d[i]; lbs = i; }

    __shared__ float bv[256];
    __shared__ int   bi[256];
    __shared__ int   s_sel[Kp];
    __shared__ int   s_cur;

    for (int r = 0; r < Kp; r++) {
        bv[t] = lbv;
        bi[t] = t + (lbs << 8);
        __syncthreads();
        if (t < 32) {
            float v = bv[t]; int id = bi[t];
            #pragma unroll
            for (int j = 1; j < 8; j++) {
                float v2 = bv[t + 32 * j]; int i2 = bi[t + 32 * j];
                if (v2 < v || (v2 == v && i2 < id)) { v = v2; id = i2; }
            }
            #pragma unroll
            for (int off = 16; off > 0; off >>= 1) {
                float v2 = __shfl_down_sync(0xffffffffu, v, off);
                int   i2 = __shfl_down_sync(0xffffffffu, id, off);
                if (v2 < v || (v2 == v && i2 < id)) { v = v2; id = i2; }
            }
            if (t == 0) { s_sel[r] = id; s_cur = id; }
        }
        __syncthreads();
        int cid = s_cur;
        if ((cid & 255) == t) {
            int slot = cid >> 8;
            #pragma unroll
            for (int i = 0; i < 32; i++) if (i == slot) d[i] = 3.0e38f;
            lbv = d[0]; lbs = 0;
            #pragma unroll
            for (int i = 1; i < 32; i++) if (d[i] < lbv) { lbv = d[i]; lbs = i; }
        }
    }
    if (t < Kp) g_knn[bs * Kp + t] = s_sel[t];
}

// ---------------------------------------------------------------------------
// Kernel 3: MLP stack as SGEMM. One CTA = 2 queries (64 rows), 128 threads.
// Activations in smem k-major [c][m] (stride RP). Weights c-major, staged
// into swB coalesced per K-chunk. 8x8 register tile per thread.
// ---------------------------------------------------------------------------
#define SMEM_BUF_F (C1P * RP)         // 8976 floats: feats -> h2
#define SMEM_BUF_H (M0 * RP)          // 8704 floats: h1 -> h3-half
#define SMEM_SWB   (16 * 128)         // 2048 floats
#define SMEM_SWM   (QB * Kp * HIDp)   // 512 floats
#define SMEM_FLOATS (SMEM_BUF_F + SMEM_BUF_H + SMEM_SWB + SMEM_SWM)
#define SMEM_BYTES  (SMEM_FLOATS * 4 + RR * 4)

template<int C, int BK>
__device__ __forceinline__ void gemm_layer(
    const float* __restrict__ Asrc,   // smem [C][RP]
    const float* __restrict__ Wsrc,   // global c-major [C][wstride]
    int wstride, int woff,
    float* __restrict__ swB,          // smem [BK][128]
    float* __restrict__ dest,         // smem [128][RP]
    int t, int o0, int o1, int m0, int m1)
{
    float acc[8][8];                  // [o][m]
    #pragma unroll
    for (int j = 0; j < 8; j++)
        #pragma unroll
        for (int i = 0; i < 8; i++) acc[j][i] = 0.0f;

    #pragma unroll 1
    for (int c0 = 0; c0 < C; c0 += BK) {
        __syncthreads();
        #pragma unroll
        for (int idx = 4 * t; idx < BK * 128; idx += 512) {
            int r = idx >> 7, o = idx & 127;
            *(float4*)&swB[idx] = *(const float4*)&Wsrc[(size_t)(c0 + r) * wstride + woff + o];
        }
        __syncthreads();
        #pragma unroll
        for (int kk = 0; kk < BK; kk++) {
            const float* arow = Asrc + (c0 + kk) * RP;
            float4 a0 = *(const float4*)&arow[m0];
            float4 a1 = *(const float4*)&arow[m1];
            float4 b0 = *(const float4*)&swB[kk * 128 + o0];
            float4 b1 = *(const float4*)&swB[kk * 128 + o1];
            float am[8] = {a0.x, a0.y, a0.z, a0.w, a1.x, a1.y, a1.z, a1.w};
            float bo[8] = {b0.x, b0.y, b0.z, b0.w, b1.x, b1.y, b1.z, b1.w};
            #pragma unroll
            for (int j = 0; j < 8; j++)
                #pragma unroll
                for (int i = 0; i < 8; i++)
                    acc[j][i] = fmaf(bo[j], am[i], acc[j][i]);
        }
    }
    __syncthreads();   // all reads of Asrc/swB done before dest (may alias next stage) is written
    #pragma unroll
    for (int j = 0; j < 8; j++) {
        int o = (j < 4) ? (o0 + j) : (o1 + j - 4);
        float4 v0, v1;
        v0.x = lrelu(acc[j][0]); v0.y = lrelu(acc[j][1]);
        v0.z = lrelu(acc[j][2]); v0.w = lrelu(acc[j][3]);
        v1.x = lrelu(acc[j][4]); v1.y = lrelu(acc[j][5]);
        v1.z = lrelu(acc[j][6]); v1.w = lrelu(acc[j][7]);
        *(float4*)&dest[o * RP + m0] = v0;
        *(float4*)&dest[o * RP + m1] = v1;
    }
}

__global__ void __launch_bounds__(128) mlp_kernel(const float* __restrict__ xyz,
    const float* __restrict__ wn1, const float* __restrict__ wb1,
    const float* __restrict__ wn2, const float* __restrict__ wb2,
    const float* __restrict__ wn3, const float* __restrict__ wb3)
{
    extern __shared__ float sm[];
    float* bufF = sm;                          // [132][RP]  feats -> h2
    float* bufH = bufF + SMEM_BUF_F;           // [128][RP]  h1 -> h3-half
    float* swB  = bufH + SMEM_BUF_H;           // [16][128]
    float* swm  = swB + SMEM_SWB;              // [64][8]
    int*   sidx = (int*)(swm + SMEM_SWM);      // [64]

    const int pair = blockIdx.x;               // 0..8191
    const int b    = pair >> 10;               // same b for both queries
    const int t    = threadIdx.x;
    const int tx = t & 15, ty = t >> 4;
    const int o0 = tx * 4, o1 = tx * 4 + 64;
    const int m0 = ty * 4, m1 = ty * 4 + 32;

    const float* X  = xyz + (size_t)b * 3 * Np;
    const float* PT = g_ptsT + (size_t)b * Np * Dp;

    if (t < RR) sidx[t] = g_knn[(size_t)(pair * 2 + (t >> 5)) * Kp + (t & 31)];
    __syncthreads();

    // gather point features: row c=3+t, columns m
    #pragma unroll 4
    for (int m = 0; m < RR; m++) {
        int n = sidx[m];
        bufF[(3 + t) * RP + m] = PT[(size_t)n * Dp + t];
    }
    // direction rows 0..2 (192 entries) + zero row 131
    for (int idx = t; idx < RR * 3; idx += 128) {
        int m = idx / 3, c = idx - m * 3;
        int n = sidx[m];
        int sq = ((pair * 2 + (m >> 5)) & (Sp - 1));
        bufF[c * RP + m] = X[c * Np + n] - X[c * Np + sq];
    }
    if (t < RR) bufF[C0 * RP + t] = 0.0f;   // row 131
    __syncthreads();

    // weightnet: thread t<64 handles m=t -> swm[m][0..7]
    if (t < RR) {
        float dx = bufF[0 * RP + t], dy = bufF[1 * RP + t], dz = bufF[2 * RP + t];
        float h[8], g[8];
        #pragma unroll
        for (int o = 0; o < 8; o++) {
            float a = wn1[o * 3 + 0] * dx + wn1[o * 3 + 1] * dy + wn1[o * 3 + 2] * dz + wb1[o];
            h[o] = a > 0.0f ? a : 0.0f;
        }
        #pragma unroll
        for (int o = 0; o < 8; o++) {
            float a = wb2[o];
            #pragma unroll
            for (int c = 0; c < 8; c++) a += wn2[o * 8 + c] * h[c];
            g[o] = a > 0.0f ? a : 0.0f;
        }
        #pragma unroll
        for (int o = 0; o < 8; o++) {
            float a = wb3[o];
            #pragma unroll
            for (int c = 0; c < 8; c++) a += wn3[o * 8 + c] * g[c];
            swm[t * 8 + o] = a > 0.0f ? a : 0.0f;
        }
    }

    // layer 1: bufF[132][m] x w1T -> h1 in bufH
    gemm_layer<C1P, 12>(bufF, g_w1T, 128, 0, swB, bufH, t, o0, o1, m0, m1);
    __syncthreads();
    // layer 2: bufH x w2T -> h2 in bufF (feats dead; weightnet reads long done)
    gemm_layer<M0, 16>(bufH, g_w2T, 128, 0, swB, bufF, t, o0, o1, m0, m1);
    __syncthreads();

    // layer 3 in two halves of 128 outputs; agg after each half
    #pragma unroll 1
    for (int p = 0; p < 2; p++) {
        gemm_layer<M1, 16>(bufF, g_w3T, 256, 128 * p, swB, bufH, t, o0, o1, m0, m1);
        __syncthreads();
        // agg: agg[q][128p+o][w] = sum_k h3[o][q*32+k] * swm[q*32+k][w]
        {
            int q  = t >> 6;
            int ob = t & 63;
            int gq = pair * 2 + q;
            float* fo = g_flat + (size_t)gq * FLATN + (size_t)(128 * p) * 8;
            const float* wmq = swm + q * Kp * 8;
            #pragma unroll
            for (int oo = 0; oo < 2; oo++) {
                int o = ob + 64 * oo;
                const float* hrow = bufH + o * RP + q * Kp;
                float ag[8];
                #pragma unroll
                for (int w = 0; w < 8; w++) ag[w] = 0.0f;
                #pragma unroll 4
                for (int k = 0; k < Kp; k++) {
                    float h = hrow[k];
                    float4 wa = *(const float4*)&wmq[k * 8];
                    float4 wb = *(const float4*)&wmq[k * 8 + 4];
                    ag[0] = fmaf(h, wa.x, ag[0]); ag[1] = fmaf(h, wa.y, ag[1]);
                    ag[2] = fmaf(h, wa.z, ag[2]); ag[3] = fmaf(h, wa.w, ag[3]);
                    ag[4] = fmaf(h, wb.x, ag[4]); ag[5] = fmaf(h, wb.y, ag[5]);
                    ag[6] = fmaf(h, wb.z, ag[6]); ag[7] = fmaf(h, wb.w, ag[7]);
                }
                *(float4*)&fo[o * 8]     = make_float4(ag[0], ag[1], ag[2], ag[3]);
                *(float4*)&fo[o * 8 + 4] = make_float4(ag[4], ag[5], ag[6], ag[7]);
            }
        }
        __syncthreads();
    }
}

// ---------------------------------------------------------------------------
// Kernel 4: out = lrelu(flat[16384,2048] @ wlin[256,2048]^T) -> out[b][o][s]
// ---------------------------------------------------------------------------
#define BM 64
#define BN 64
#define BKk 16

__global__ void __launch_bounds__(256) out_gemm_kernel(
    const float* __restrict__ Wl, float* __restrict__ outp)
{
    __shared__ float As[BKk][BM];
    __shared__ float Bs[BKk][BN];

    const int bm = blockIdx.x;
    const int bn = blockIdx.y;
    const int t  = threadIdx.x;
    const int mm0 = bm * BM, nn0 = bn * BN;
    const int tx = t & 15, ty = t >> 4;
    const int lr = t >> 2;
    const int lc = (t & 3) * 4;

    const float* A = g_flat;

    float acc[4][4];
    #pragma unroll
    for (int i = 0; i < 4; i++)
        #pragma unroll
        for (int j = 0; j < 4; j++) acc[i][j] = 0.0f;

    for (int k0 = 0; k0 < FLATN; k0 += BKk) {
        float4 a = *(const float4*)(A + (size_t)(mm0 + lr) * FLATN + k0 + lc);
        As[lc + 0][lr] = a.x; As[lc + 1][lr] = a.y; As[lc + 2][lr] = a.z; As[lc + 3][lr] = a.w;
        float4 bq = *(const float4*)(Wl + (size_t)(nn0 + lr) * FLATN + k0 + lc);
        Bs[lc + 0][lr] = bq.x; Bs[lc + 1][lr] = bq.y; Bs[lc + 2][lr] = bq.z; Bs[lc + 3][lr] = bq.w;
        __syncthreads();
        #pragma unroll
        for (int k = 0; k < BKk; k++) {
            float4 av = *(const float4*)&As[k][ty * 4];
            float4 bv = *(const float4*)&Bs[k][tx * 4];
            float aa[4] = {av.x, av.y, av.z, av.w};
            float bb[4] = {bv.x, bv.y, bv.z, bv.w};
            #pragma unroll
            for (int i = 0; i < 4; i++)
                #pragma unroll
                for (int j = 0; j < 4; j++)
                    acc[i][j] += aa[i] * bb[j];
        }
        __syncthreads();
    }

    #pragma unroll
    for (int i = 0; i < 4; i++) {
        int mm = mm0 + ty * 4 + i;
        int bb = mm >> 11, ss = mm & (Sp - 1);
        float* ob = outp + (size_t)bb * M2 * Sp + ss;
        #pragma unroll
        for (int j = 0; j < 4; j++) {
            ob[(size_t)(nn0 + tx * 4 + j) * Sp] = lrelu(acc[i][j]);
        }
    }
}

// ---------------------------------------------------------------------------
// Launcher
// ---------------------------------------------------------------------------
extern "C" void kernel_launch(void* const* d_in, const int* in_sizes, int n_in,
                              void* d_out, int out_size)
{
    const float* xyz  = (const float*)d_in[0];
    const float* pts  = (const float*)d_in[1];
    const float* w1   = (const float*)d_in[2];
    const float* w2   = (const float*)d_in[3];
    const float* w3   = (const float*)d_in[4];
    const float* wn1  = (const float*)d_in[5];
    const float* wb1  = (const float*)d_in[6];
    const float* wn2  = (const float*)d_in[7];
    const float* wb2  = (const float*)d_in[8];
    const float* wn3  = (const float*)d_in[9];
    const float* wb3  = (const float*)d_in[10];
    const float* wlin = (const float*)d_in[11];
    float* out = (float*)d_out;

    prep_w1T_kernel<<<(C1P * M0 + 255) / 256, 256>>>(w1);
    prep_w2T_kernel<<<(M0 * M1 + 255) / 256, 256>>>(w2);
    prep_w3T_kernel<<<(M1 * M2 + 255) / 256, 256>>>(w3);

    copy_newxyz_kernel<<<(Bb * 3 * Sp + 255) / 256, 256>>>(xyz, out);

    {
        dim3 g(Np / 32, Dp / 32, Bb);
        dim3 blk(32, 8);
        transpose_kernel<<<g, blk>>>(pts);
    }

    knn_kernel<<<Bb * Sp, 256>>>(xyz);

    cudaFuncSetAttribute(mlp_kernel, cudaFuncAttributeMaxDynamicSharedMemorySize, SMEM_BYTES);
    mlp_kernel<<<Bb * Sp / QB, 128, SMEM_BYTES>>>(xyz,
                                                  wn1, wb1, wn2, wb2, wn3, wb3);

    {
        dim3 g((Bb * Sp) / BM, M2 / BN);
        out_gemm_kernel<<<g, 256>>>(wlin, out + Bb * 3 * Sp);
    }
}